// round 7
// baseline (speedup 1.0000x reference)
#include <cuda_runtime.h>
#include <math.h>

#define B_N   8
#define T_LEN 48000
#define MAX_H 60
#define C_N   100
#define NFORM 5

// ReduceWindowRewriter(base=16) level sizes for n=48000:
//  L0: 48000 elems -> 3000 tiles of 16
//  L1: 3000 sums   -> pad 3008 -> 188 tiles of 16
//  L2: 188 sums    -> pad 192  -> 12 tiles of 16
//  L3: 12 sums     -> naive sequential scan
#define L1_N   3000
#define L1_PAD 3008
#define L2_N   188
#define L2_PAD 192
#define L3_N   12

__device__ float g_phase[B_N][T_LEN];

// 2*pi split: C1 = fl32(2*pi), C2 = 2*pi - C1 (negative)
#define TWOPI_F   6.28318548202514648f
#define C2_ABS    1.7484556e-7f      /* -(2pi - fl32(2pi)) */
#define INV2PI_F  0.15915494309189535f

// ---------------------------------------------------------------------------
// Kernel 1: XLA cumsum = reduce_window + ReduceWindowRewriter(base=16).
// Bit-exact f32 replica. Elementwise increment replicates XLA's
// divide-by-constant -> multiply-by-reciprocal rewrite (two roundings, no
// constant folding):
//   x[t]     = fl( fl( fl32(2pi) * f0[t] ) * fl32(1/24000) )
//   inner0   = sequential left fold within each 16-tile (acc starts at 0)
//   S_k[i]   = fl( inner_k[i] + S_{k+1}[i/16 - 1] ),  first tile adds 0
//   phase[t] = fl( S0[t] + initial_phase )
// One CTA per batch.
// ---------------------------------------------------------------------------
__global__ void __launch_bounds__(1024)
phase_scan_kernel(const float* __restrict__ f0,
                  const float* __restrict__ initial_phase,
                  float* __restrict__ out /* final_phase at tail */)
{
    int b   = blockIdx.x;
    int tid = threadIdx.x;

    __shared__ float sT1[L1_PAD];   // tile sums L0 -> inner1 (in-place)
    __shared__ float sT2[L2_PAD];   // tile sums L1 -> inner2 (in-place)
    __shared__ float sT3[L3_N];     // tile sums L2 -> S3 (in-place)
    __shared__ float sS2[L2_N];
    __shared__ float sS1[L1_N];

    const float* f0b = f0 + b * T_LEN;
    const float INV_SR = 1.0f / 24000.0f;   // fl32(1/24000), compile-time RN

    // Level 0: per-16-tile sequential inclusive scan; store inner0, tile sums.
    for (int j = tid; j < L1_N; j += 1024) {
        float acc = 0.0f;
        int base = j * 16;
        #pragma unroll
        for (int k = 0; k < 16; k++) {
            float v = __fmul_rn(TWOPI_F, f0b[base + k]);
            float x = __fmul_rn(v, INV_SR);
            acc = __fadd_rn(acc, x);
            g_phase[b][base + k] = acc;   // inner0 (pre-exclusive-add)
        }
        sT1[j] = acc;
    }
    if (tid >= L1_N && tid < L1_PAD) sT1[tid] = 0.0f;   // pad with init=0
    __syncthreads();

    // Level 1: 188 tiles of 16 over sT1; in-place inner1, sums to sT2.
    for (int j2 = tid; j2 < L2_N; j2 += 1024) {
        float acc = 0.0f;
        int base = j2 * 16;
        #pragma unroll
        for (int k = 0; k < 16; k++) {
            acc = __fadd_rn(acc, sT1[base + k]);
            sT1[base + k] = acc;          // inner1
        }
        sT2[j2] = acc;
    }
    if (tid >= L2_N && tid < L2_PAD) sT2[tid] = 0.0f;
    __syncthreads();

    // Level 2: 12 tiles of 16 over sT2; in-place inner2, sums to sT3.
    if (tid < L3_N) {
        float acc = 0.0f;
        int base = tid * 16;
        #pragma unroll
        for (int k = 0; k < 16; k++) {
            acc = __fadd_rn(acc, sT2[base + k]);
            sT2[base + k] = acc;          // inner2
        }
        sT3[tid] = acc;
    }
    __syncthreads();

    // Level 3: naive sequential inclusive scan of the 12 sums (<= base).
    if (tid == 0) {
        float acc = 0.0f;
        #pragma unroll
        for (int i = 0; i < L3_N; i++) {
            acc = __fadd_rn(acc, sT3[i]);
            sT3[i] = acc;                 // S3
        }
    }
    __syncthreads();

    // Compose S2 = inner2 + exclusive(S3)
    if (tid < L2_N) {
        int j3 = tid >> 4;
        sS2[tid] = j3 ? __fadd_rn(sT2[tid], sT3[j3 - 1]) : sT2[tid];
    }
    __syncthreads();

    // Compose S1 = inner1 + exclusive(S2)
    for (int j = tid; j < L1_N; j += 1024) {
        int j2 = j >> 4;
        sS1[j] = j2 ? __fadd_rn(sT1[j], sS2[j2 - 1]) : sT1[j];
    }
    __syncthreads();

    // Compose S0 and add initial_phase: phase[t] = fl(fl(inner0+S1[j-1]) + ip)
    float ipb = initial_phase[b];
    for (int t = tid; t < T_LEN; t += 1024) {
        int j = t >> 4;
        float s0 = g_phase[b][t];
        if (j) s0 = __fadd_rn(s0, sS1[j - 1]);
        g_phase[b][t] = __fadd_rn(s0, ipb);
    }
    __syncthreads();

    // final_phase = phase[:, -1] % (2*pi)  (fmod exact, operands positive)
    if (tid == 0) {
        out[B_N * T_LEN + b] = fmodf(g_phase[b][T_LEN - 1], TWOPI_F);
    }
}

// ---------------------------------------------------------------------------
// Kernel 2: main oscillator. One thread per (b, t).
// ---------------------------------------------------------------------------
__global__ void __launch_bounds__(256)
osc_kernel(const float* __restrict__ f0,
           const float* __restrict__ amplitudes,
           const float* __restrict__ formant_freqs,
           const float* __restrict__ formant_bws,
           const float* __restrict__ formant_amps,
           float* __restrict__ out)
{
    int idx = blockIdx.x * blockDim.x + threadIdx.x;
    if (idx >= B_N * T_LEN) return;
    int b = idx / T_LEN;
    int t = idx - b * T_LEN;

    float f0v   = f0[idx];
    float phase = g_phase[b][t];

    // Linear interp of formant params (align_corners=True), exact f32 replica.
    const float SRC_SCALE = (float)(99.0 / 47999.0);
    float src = __fmul_rn((float)t, SRC_SCALE);
    int i0 = (int)floorf(src);
    i0 = max(0, min(C_N - 2, i0));
    float frac = __fsub_rn(src, (float)i0);
    float w0   = __fsub_rn(1.0f, frac);

    const float* fq = formant_freqs + (b * C_N + i0) * NFORM;
    const float* fb = formant_bws   + (b * C_N + i0) * NFORM;
    const float* fa = formant_amps  + (b * C_N + i0) * NFORM;

    // Pre-scaled per-formant params: exact power-of-2 scaling (2^-8 / 2^-16)
    // so the 5-term den/num products stay in f32 range.
    float freq_s[NFORM], bw2_s[NFORM], num_s[NFORM];
    #pragma unroll
    for (int f = 0; f < NFORM; f++) {
        float fr = __fadd_rn(__fmul_rn(fq[f], w0), __fmul_rn(fq[f + NFORM], frac));
        float bw = __fadd_rn(__fmul_rn(fb[f], w0), __fmul_rn(fb[f + NFORM], frac));
        float am = __fadd_rn(__fmul_rn(fa[f], w0), __fmul_rn(fa[f + NFORM], frac));
        float bw2 = __fmul_rn(bw, bw);
        float num = __fmul_rn(__fmul_rn(am, bw), bw);      // amp*bw*bw, ref order
        freq_s[f] = __fmul_rn(fr,  0.00390625f);           // * 2^-8  (exact)
        bw2_s[f]  = __fmul_rn(bw2, 1.52587890625e-05f);    // * 2^-16 (exact)
        num_s[f]  = __fmul_rn(num, 1.52587890625e-05f);    // * 2^-16 (exact)
    }

    const float* arow = amplitudes + (size_t)idx * MAX_H;   // 240B row, 16B aligned
    float acc = 0.0f;

    for (int hc = 0; hc < MAX_H; hc += 4) {
        // If the first harmonic of this chunk is cut, all later ones are too
        // (fl(f0*h) strictly increasing in h at these magnitudes).
        if (!(__fmul_rn(f0v, (float)(hc + 1)) < 12000.0f)) break;
        float4 a4 = *reinterpret_cast<const float4*>(arow + hc);
        float am[4] = {a4.x, a4.y, a4.z, a4.w};

        #pragma unroll
        for (int i = 0; i < 4; i++) {
            float hf    = (float)(hc + i + 1);
            float hfreq = __fmul_rn(f0v, hf);       // exact ref h_freq
            if (hfreq < 12000.0f) {
                // sin of the EXACT f32 product phase*h; 2-FMA Cody-Waite.
                float arg = __fmul_rn(phase, hf);
                float kq  = rintf(__fmul_rn(arg, INV2PI_F));   // k <= ~55000
                float r   = __fmaf_rn(kq, -TWOPI_F, arg);
                r         = __fmaf_rn(kq,  C2_ABS,  r);
                float sv  = __sinf(r);                         // |r| <= pi+5e-3

                // factor = prod_f (den+num)/den  -> single fast division
                float hfs = __fmul_rn(hfreq, 0.00390625f);     // * 2^-8 (exact)
                float Np = 1.0f, Dp = 1.0f;
                #pragma unroll
                for (int f = 0; f < NFORM; f++) {
                    float d   = __fsub_rn(hfs, freq_s[f]);
                    float den = __fmaf_rn(d, d, bw2_s[f]);
                    float nd  = __fadd_rn(den, num_s[f]);
                    Np = __fmul_rn(Np, nd);
                    Dp = __fmul_rn(Dp, den);
                }
                float fact = __fdividef(Np, Dp);

                acc = __fmaf_rn(__fmul_rn(am[i], sv), fact, acc);
            }
        }
    }

    float voiced = (f0v > 0.0f) ? 1.0f : 0.0f;
    out[idx] = __fmul_rn(acc, voiced);
}

// ---------------------------------------------------------------------------
// Inputs (metadata order): f0 [B,T,1], amplitudes [B,T,60],
// formant_freqs [B,100,5], formant_bws [B,100,5], formant_amps [B,100,5],
// initial_phase [B,1,1].
// Output: signal [B,T] (384000 floats) then final_phase [B,1,1] (8 floats).
// ---------------------------------------------------------------------------
extern "C" void kernel_launch(void* const* d_in, const int* in_sizes, int n_in,
                              void* d_out, int out_size)
{
    const float* f0   = (const float*)d_in[0];
    const float* amps = (const float*)d_in[1];
    const float* ffq  = (const float*)d_in[2];
    const float* fbw  = (const float*)d_in[3];
    const float* fam  = (const float*)d_in[4];
    const float* ip   = (const float*)d_in[5];
    float* out = (float*)d_out;

    phase_scan_kernel<<<B_N, 1024>>>(f0, ip, out);

    int total = B_N * T_LEN;
    int threads = 256;
    int blocks = (total + threads - 1) / threads;
    osc_kernel<<<blocks, threads>>>(f0, amps, ffq, fbw, fam, out);
}

// round 8
// speedup vs baseline: 1.6903x; 1.6903x over previous
#include <cuda_runtime.h>
#include <math.h>

#define B_N   8
#define T_LEN 48000
#define MAX_H 60
#define C_N   100
#define NFORM 5

// ReduceWindowRewriter(base=16) level sizes for n=48000:
//  L0: 48000 -> 3000 tiles of 16 ; L1: 3000 (pad 3008) -> 188 ;
//  L2: 188 (pad 192) -> 12 ; L3: 12 naive sequential.
#define L1_N   3000
#define L1_PAD 3008
#define L2_N   188
#define L2_PAD 192
#define L3_N   12

__device__ float g_inner0[B_N][T_LEN];       // per-16-tile inclusive scans
__device__ float g_T1[B_N * L1_N];           // tile sums
__device__ float g_S1[B_N * L1_N];           // composed level-1 scan

// 2*pi split: C1 = fl32(2*pi), C2 = 2*pi - C1 (negative)
#define TWOPI_F   6.28318548202514648f
#define C2_ABS    1.7484556e-7f      /* -(2pi - fl32(2pi)) */
#define INV2PI_F  0.15915494309189535f

// ---------------- packed f32x2 helpers (per-lane IEEE RN) -------------------
typedef unsigned long long u64;
__device__ __forceinline__ u64 pk2(float lo, float hi) {
    u64 r; asm("mov.b64 %0, {%1, %2};" : "=l"(r) : "f"(lo), "f"(hi)); return r;
}
__device__ __forceinline__ void unpk2(u64 v, float& lo, float& hi) {
    asm("mov.b64 {%0, %1}, %2;" : "=f"(lo), "=f"(hi) : "l"(v));
}
__device__ __forceinline__ u64 add2(u64 a, u64 b) {
    u64 r; asm("add.rn.f32x2 %0, %1, %2;" : "=l"(r) : "l"(a), "l"(b)); return r;
}
__device__ __forceinline__ u64 mul2(u64 a, u64 b) {
    u64 r; asm("mul.rn.f32x2 %0, %1, %2;" : "=l"(r) : "l"(a), "l"(b)); return r;
}
__device__ __forceinline__ u64 fma2(u64 a, u64 b, u64 c) {
    u64 r; asm("fma.rn.f32x2 %0, %1, %2, %3;" : "=l"(r) : "l"(a), "l"(b), "l"(c)); return r;
}

// ---------------------------------------------------------------------------
// Kernel A: level-0 tiles. One thread per 16-tile (24000 tiles total).
// x[t] = fl( fl(fl32(2pi)*f0) * fl32(1/24000) ); sequential fold per tile.
// ---------------------------------------------------------------------------
__global__ void __launch_bounds__(256)
scan_tiles_kernel(const float* __restrict__ f0)
{
    int gid = blockIdx.x * blockDim.x + threadIdx.x;
    if (gid >= B_N * L1_N) return;
    int b = gid / L1_N;
    int j = gid - b * L1_N;
    const float INV_SR = 1.0f / 24000.0f;

    const float4* src = reinterpret_cast<const float4*>(f0 + b * T_LEN + j * 16);
    float4* dst = reinterpret_cast<float4*>(&g_inner0[b][j * 16]);

    float acc = 0.0f;
    #pragma unroll
    for (int q = 0; q < 4; q++) {
        float4 v = src[q];
        float o[4];
        float in[4] = {v.x, v.y, v.z, v.w};
        #pragma unroll
        for (int k = 0; k < 4; k++) {
            float x = __fmul_rn(__fmul_rn(TWOPI_F, in[k]), INV_SR);
            acc = __fadd_rn(acc, x);
            o[k] = acc;
        }
        dst[q] = make_float4(o[0], o[1], o[2], o[3]);
    }
    g_T1[gid] = acc;
}

// ---------------------------------------------------------------------------
// Kernel B: per-batch upper levels (L1..L3) + compose S1 -> global; also the
// final_phase output. One CTA per batch, 256 threads.
// ---------------------------------------------------------------------------
__global__ void __launch_bounds__(256)
scan_upper_kernel(const float* __restrict__ initial_phase,
                  float* __restrict__ out /* final_phase at tail */)
{
    int b   = blockIdx.x;
    int tid = threadIdx.x;
    __shared__ float sT1[L1_PAD];
    __shared__ float sT2[L2_PAD];
    __shared__ float sT3[L3_N];
    __shared__ float sS2[L2_N];

    for (int j = tid; j < L1_N; j += 256) sT1[j] = g_T1[b * L1_N + j];
    for (int j = L1_N + tid; j < L1_PAD; j += 256) sT1[j] = 0.0f;
    __syncthreads();

    // L1: 188 tiles of 16, sequential fold, in-place inner1.
    if (tid < L2_N) {
        float acc = 0.0f;
        int base = tid * 16;
        #pragma unroll
        for (int k = 0; k < 16; k++) {
            acc = __fadd_rn(acc, sT1[base + k]);
            sT1[base + k] = acc;
        }
        sT2[tid] = acc;
    }
    if (tid >= L2_N && tid < L2_PAD) sT2[tid] = 0.0f;
    __syncthreads();

    // L2: 12 tiles of 16.
    if (tid < L3_N) {
        float acc = 0.0f;
        int base = tid * 16;
        #pragma unroll
        for (int k = 0; k < 16; k++) {
            acc = __fadd_rn(acc, sT2[base + k]);
            sT2[base + k] = acc;
        }
        sT3[tid] = acc;
    }
    __syncthreads();

    // L3: naive sequential scan of 12.
    if (tid == 0) {
        float acc = 0.0f;
        #pragma unroll
        for (int i = 0; i < L3_N; i++) {
            acc = __fadd_rn(acc, sT3[i]);
            sT3[i] = acc;
        }
    }
    __syncthreads();

    // S2 = inner2 + exclusive(S3)
    if (tid < L2_N) {
        int j3 = tid >> 4;
        sS2[tid] = j3 ? __fadd_rn(sT2[tid], sT3[j3 - 1]) : sT2[tid];
    }
    __syncthreads();

    // S1 = inner1 + exclusive(S2) -> global
    for (int j = tid; j < L1_N; j += 256) {
        int j2 = j >> 4;
        g_S1[b * L1_N + j] = j2 ? __fadd_rn(sT1[j], sS2[j2 - 1]) : sT1[j];
    }
    __syncthreads();

    // final_phase = fl(fl(fl(inner0[T-1] + S1[2998]) + ip)) % 2pi
    if (tid == 0) {
        float s1v = __fadd_rn(sT1[2998], sS2[186]);       // S1[2998]
        float s0  = __fadd_rn(g_inner0[b][T_LEN - 1], s1v);
        float ph  = __fadd_rn(s0, initial_phase[b]);
        out[B_N * T_LEN + b] = fmodf(ph, TWOPI_F);
    }
}

// ---------------------------------------------------------------------------
// Kernel C: oscillator. One thread per (b, t). Composes phase on the fly:
//   phase = fl( fl(inner0[t] + S1[t/16 - 1]) + initial_phase )
// Formant chain evaluated for harmonic PAIRS with f32x2 packed RN math
// (bit-identical per lane to the scalar version).
// ---------------------------------------------------------------------------
__global__ void __launch_bounds__(256)
osc_kernel(const float* __restrict__ f0,
           const float* __restrict__ amplitudes,
           const float* __restrict__ formant_freqs,
           const float* __restrict__ formant_bws,
           const float* __restrict__ formant_amps,
           const float* __restrict__ initial_phase,
           float* __restrict__ out)
{
    int idx = blockIdx.x * blockDim.x + threadIdx.x;
    if (idx >= B_N * T_LEN) return;
    int b = idx / T_LEN;
    int t = idx - b * T_LEN;

    float f0v = f0[idx];

    // Compose phase (bit-exact rw16 result).
    int jt = t >> 4;
    float s0 = g_inner0[b][t];
    if (jt) s0 = __fadd_rn(s0, g_S1[b * L1_N + jt - 1]);
    float phase = __fadd_rn(s0, initial_phase[b]);

    // Linear interp of formant params (align_corners=True), exact f32 replica.
    const float SRC_SCALE = (float)(99.0 / 47999.0);
    float src = __fmul_rn((float)t, SRC_SCALE);
    int i0 = (int)floorf(src);
    i0 = max(0, min(C_N - 2, i0));
    float frac = __fsub_rn(src, (float)i0);
    float w0   = __fsub_rn(1.0f, frac);

    const float* fq = formant_freqs + (b * C_N + i0) * NFORM;
    const float* fb = formant_bws   + (b * C_N + i0) * NFORM;
    const float* fa = formant_amps  + (b * C_N + i0) * NFORM;

    // Packed per-formant params (negated freq so packed sub == add).
    u64 nfreq2[NFORM], bw22[NFORM], num2[NFORM];
    #pragma unroll
    for (int f = 0; f < NFORM; f++) {
        float fr = __fadd_rn(__fmul_rn(fq[f], w0), __fmul_rn(fq[f + NFORM], frac));
        float bw = __fadd_rn(__fmul_rn(fb[f], w0), __fmul_rn(fb[f + NFORM], frac));
        float am = __fadd_rn(__fmul_rn(fa[f], w0), __fmul_rn(fa[f + NFORM], frac));
        float bw2 = __fmul_rn(bw, bw);
        float num = __fmul_rn(__fmul_rn(am, bw), bw);            // ref order
        float nfs = -__fmul_rn(fr,  0.00390625f);                // -(freq*2^-8)
        float b2s = __fmul_rn(bw2, 1.52587890625e-05f);          // *2^-16 exact
        float nms = __fmul_rn(num, 1.52587890625e-05f);
        nfreq2[f] = pk2(nfs, nfs);
        bw22[f]   = pk2(b2s, b2s);
        num2[f]   = pk2(nms, nms);
    }
    const u64 ONE2 = pk2(1.0f, 1.0f);

    const float* arow = amplitudes + (size_t)idx * MAX_H;   // 240B row, 16B ok
    float acc = 0.0f;

    for (int hc = 0; hc < MAX_H; hc += 4) {
        if (!(__fmul_rn(f0v, (float)(hc + 1)) < 12000.0f)) break;
        float4 a4 = *reinterpret_cast<const float4*>(arow + hc);
        float am4[4] = {a4.x, a4.y, a4.z, a4.w};

        #pragma unroll
        for (int p = 0; p < 2; p++) {
            float hf0 = (float)(hc + 2 * p + 1);
            float hf1 = (float)(hc + 2 * p + 2);
            float hq0 = __fmul_rn(f0v, hf0);
            float hq1 = __fmul_rn(f0v, hf1);
            bool  m0  = hq0 < 12000.0f;
            bool  m1  = hq1 < 12000.0f;
            if (!m0) break;                        // monotone: m1 false too

            // Packed formant chain for the pair (bit-identical per lane).
            u64 hfs2 = pk2(__fmul_rn(hq0, 0.00390625f),
                           __fmul_rn(hq1, 0.00390625f));
            u64 Np2 = ONE2, Dp2 = ONE2;
            #pragma unroll
            for (int f = 0; f < NFORM; f++) {
                u64 d2   = add2(hfs2, nfreq2[f]);          // hfs - freq
                u64 den2 = fma2(d2, d2, bw22[f]);
                u64 nd2  = add2(den2, num2[f]);
                Np2 = mul2(Np2, nd2);
                Dp2 = mul2(Dp2, den2);
            }
            float Np0, Np1, Dp0, Dp1;
            unpk2(Np2, Np0, Np1);
            unpk2(Dp2, Dp0, Dp1);

            // sin of EXACT f32 product phase*h; 2-FMA Cody-Waite + fast sin.
            float arg0 = __fmul_rn(phase, hf0);
            float kq0  = rintf(__fmul_rn(arg0, INV2PI_F));
            float r0   = __fmaf_rn(kq0, -TWOPI_F, arg0);
            r0         = __fmaf_rn(kq0,  C2_ABS,  r0);
            float sv0  = __sinf(r0);

            float arg1 = __fmul_rn(phase, hf1);
            float kq1  = rintf(__fmul_rn(arg1, INV2PI_F));
            float r1   = __fmaf_rn(kq1, -TWOPI_F, arg1);
            r1         = __fmaf_rn(kq1,  C2_ABS,  r1);
            float sv1  = __sinf(r1);

            float fact0 = __fdividef(Np0, Dp0);
            float fact1 = __fdividef(Np1, Dp1);

            acc = __fmaf_rn(__fmul_rn(am4[2 * p], sv0), fact0, acc);
            if (m1)
                acc = __fmaf_rn(__fmul_rn(am4[2 * p + 1], sv1), fact1, acc);
        }
    }

    float voiced = (f0v > 0.0f) ? 1.0f : 0.0f;
    out[idx] = __fmul_rn(acc, voiced);
}

// ---------------------------------------------------------------------------
// Inputs (metadata order): f0 [B,T,1], amplitudes [B,T,60],
// formant_freqs [B,100,5], formant_bws [B,100,5], formant_amps [B,100,5],
// initial_phase [B,1,1].
// Output: signal [B,T] (384000 floats) then final_phase [B,1,1] (8 floats).
// ---------------------------------------------------------------------------
extern "C" void kernel_launch(void* const* d_in, const int* in_sizes, int n_in,
                              void* d_out, int out_size)
{
    const float* f0   = (const float*)d_in[0];
    const float* amps = (const float*)d_in[1];
    const float* ffq  = (const float*)d_in[2];
    const float* fbw  = (const float*)d_in[3];
    const float* fam  = (const float*)d_in[4];
    const float* ip   = (const float*)d_in[5];
    float* out = (float*)d_out;

    int tiles = B_N * L1_N;
    scan_tiles_kernel<<<(tiles + 255) / 256, 256>>>(f0);
    scan_upper_kernel<<<B_N, 256>>>(ip, out);

    int total = B_N * T_LEN;
    osc_kernel<<<(total + 255) / 256, 256>>>(f0, amps, ffq, fbw, fam, ip, out);
}